// round 1
// baseline (speedup 1.0000x reference)
#include <cuda_runtime.h>
#include <math.h>

#define B_  2
#define T_  2048
#define D_  2048
#define H_  16
#define KV_ 4
#define HD_ 128

// Scratch (allocation-free rule: __device__ globals)
__device__ float g_q[(size_t)B_ * T_ * H_  * HD_];   // 32 MB
__device__ float g_k[(size_t)B_ * T_ * KV_ * HD_];   //  8 MB
__device__ float g_v[(size_t)B_ * T_ * KV_ * HD_];   //  8 MB
__device__ float g_o[(size_t)B_ * T_ * H_  * HD_];   // 32 MB

// ---------------------------------------------------------------------------
// SGEMM: C[M,N] = A[M,K] @ B[K,N], all row-major fp32.
// 128x128 block tile, 8-deep K tile, 8x8 per-thread micro-tile, 256 threads.
// ---------------------------------------------------------------------------
__global__ __launch_bounds__(256) void sgemm128(const float* __restrict__ A,
                                                const float* __restrict__ B,
                                                float* __restrict__ C,
                                                int M, int N, int K) {
    __shared__ float As[8][128];
    __shared__ float Bs[8][128];

    const int tid = threadIdx.x;
    const int bm = blockIdx.y * 128;
    const int bn = blockIdx.x * 128;
    const int tx = tid & 15;       // 16 thread-cols
    const int ty = tid >> 4;       // 16 thread-rows

    float c[8][8];
#pragma unroll
    for (int i = 0; i < 8; i++)
#pragma unroll
        for (int j = 0; j < 8; j++) c[i][j] = 0.f;

    // A tile loader: 128 rows x 8 cols -> 256 float4 (each thread: 1)
    const int arow = tid >> 1;
    const int acol = (tid & 1) * 4;
    // B tile loader: 8 rows x 128 cols -> 256 float4
    const int brow = tid >> 5;
    const int bcol = (tid & 31) * 4;

    const float* Ap = A + (size_t)(bm + arow) * K + acol;
    const float* Bp = B + (size_t)brow * N + bn + bcol;

    for (int k0 = 0; k0 < K; k0 += 8) {
        float4 av = *(const float4*)(Ap + k0);
        float4 bv = *(const float4*)(Bp + (size_t)k0 * N);
        As[acol + 0][arow] = av.x;
        As[acol + 1][arow] = av.y;
        As[acol + 2][arow] = av.z;
        As[acol + 3][arow] = av.w;
        *(float4*)&Bs[brow][bcol] = bv;
        __syncthreads();

#pragma unroll
        for (int kk = 0; kk < 8; kk++) {
            float a[8], b[8];
#pragma unroll
            for (int i = 0; i < 8; i += 4) {
                float4 t = *(const float4*)&As[kk][ty * 8 + i];
                a[i] = t.x; a[i + 1] = t.y; a[i + 2] = t.z; a[i + 3] = t.w;
            }
#pragma unroll
            for (int j = 0; j < 8; j += 4) {
                float4 t = *(const float4*)&Bs[kk][tx * 8 + j];
                b[j] = t.x; b[j + 1] = t.y; b[j + 2] = t.z; b[j + 3] = t.w;
            }
#pragma unroll
            for (int i = 0; i < 8; i++)
#pragma unroll
                for (int j = 0; j < 8; j++) c[i][j] += a[i] * b[j];
        }
        __syncthreads();
    }

#pragma unroll
    for (int i = 0; i < 8; i++) {
        float* Cp = C + (size_t)(bm + ty * 8 + i) * N + bn + tx * 8;
        float4 v0 = {c[i][0], c[i][1], c[i][2], c[i][3]};
        float4 v1 = {c[i][4], c[i][5], c[i][6], c[i][7]};
        *(float4*)(Cp)     = v0;
        *(float4*)(Cp + 4) = v1;
    }
}

// ---------------------------------------------------------------------------
// Fused RMSNorm (over HD=128) + interleaved-pair RoPE, in place.
// One warp per (b, t, head) row of 128. cos/sin: [T, HD] (pairwise repeated).
// ---------------------------------------------------------------------------
__global__ __launch_bounds__(256) void rmsnorm_rope_kernel(float* __restrict__ data,
                                                           const float* __restrict__ scale,
                                                           const float* __restrict__ cosT,
                                                           const float* __restrict__ sinT,
                                                           int nheads, int total_rows) {
    const int warp = threadIdx.x >> 5;
    const int lane = threadIdx.x & 31;
    const int row = blockIdx.x * 8 + warp;
    if (row >= total_rows) return;
    const int t = (row / nheads) % T_;

    float4* p = (float4*)(data + (size_t)row * HD_);
    float4 x = p[lane];
    float ss = x.x * x.x + x.y * x.y + x.z * x.z + x.w * x.w;
#pragma unroll
    for (int o = 16; o > 0; o >>= 1) ss += __shfl_xor_sync(0xffffffffu, ss, o);
    const float rinv = rsqrtf(ss * (1.0f / HD_) + 1e-6f);

    const int d0 = lane * 4;
    float4 sc = *(const float4*)(scale + d0);
    float n0 = x.x * rinv * sc.x;
    float n1 = x.y * rinv * sc.y;
    float n2 = x.z * rinv * sc.z;
    float n3 = x.w * rinv * sc.w;

    const float c0 = cosT[(size_t)t * HD_ + d0];
    const float s0 = sinT[(size_t)t * HD_ + d0];
    const float c1 = cosT[(size_t)t * HD_ + d0 + 2];
    const float s1 = sinT[(size_t)t * HD_ + d0 + 2];

    float4 r;
    r.x = n0 * c0 - n1 * s0;
    r.y = n1 * c0 + n0 * s0;
    r.z = n2 * c1 - n3 * s1;
    r.w = n3 * c1 + n2 * s1;
    p[lane] = r;
}

// ---------------------------------------------------------------------------
// Causal GQA flash attention (fp32, online softmax).
// Block = 256 threads = 8 warps; each warp owns 1 query row.
// K/V streamed in 64-row tiles through 64 KB dynamic smem.
// grid = (T/8, B*H)
// ---------------------------------------------------------------------------
__global__ __launch_bounds__(256) void flash_kernel(const float* __restrict__ q,
                                                    const float* __restrict__ k,
                                                    const float* __restrict__ v,
                                                    float* __restrict__ o) {
    extern __shared__ float sm[];
    float4* ks4 = (float4*)sm;                 // [64][32] float4
    float4* vs4 = (float4*)(sm + 64 * HD_);    // [64][32] float4

    const int tid = threadIdx.x;
    const int warp = tid >> 5;
    const int lane = tid & 31;
    const int bh = blockIdx.y;
    const int b = bh / H_;
    const int h = bh - b * H_;
    const int g = h / (H_ / KV_);
    const int m = blockIdx.x * 8 + warp;

    const float sscale = 0.08838834764831845f;  // 1/sqrt(128)
    float4 qv = *(const float4*)(q + ((size_t)(b * T_ + m) * H_ + h) * HD_ + lane * 4);
    qv.x *= sscale; qv.y *= sscale; qv.z *= sscale; qv.w *= sscale;

    float mi = -1e30f, li = 0.f;
    float4 acc = {0.f, 0.f, 0.f, 0.f};

    const int ntiles = (blockIdx.x * 8 + 7) / 64 + 1;
    for (int j = 0; j < ntiles; j++) {
        const int base = j * 64;
        // cooperative load K,V tile (64 rows x 128 floats each)
        for (int it = tid; it < 64 * 32; it += 256) {
            const int r = it >> 5, c = it & 31;
            const size_t gi = ((size_t)(b * T_ + base + r) * KV_ + g) * HD_ + c * 4;
            ks4[it] = *(const float4*)(k + gi);
            vs4[it] = *(const float4*)(v + gi);
        }
        __syncthreads();

        // scores: each lane ends up owning score columns (lane) and (lane+32)
        float s0 = -1e30f, s1 = -1e30f;
#pragma unroll
        for (int kk = 0; kk < 64; kk++) {
            float4 kv = ks4[kk * 32 + lane];
            float p = qv.x * kv.x + qv.y * kv.y + qv.z * kv.z + qv.w * kv.w;
#pragma unroll
            for (int off = 16; off > 0; off >>= 1) p += __shfl_xor_sync(0xffffffffu, p, off);
            const float sv = (base + kk <= m) ? p : -1e30f;
            if ((kk & 31) == lane) {
                if (kk < 32) s0 = sv; else s1 = sv;
            }
        }

        // online softmax update
        float tmax = fmaxf(s0, s1);
#pragma unroll
        for (int off = 16; off > 0; off >>= 1)
            tmax = fmaxf(tmax, __shfl_xor_sync(0xffffffffu, tmax, off));
        const float mnew = fmaxf(mi, tmax);
        const float alpha = __expf(mi - mnew);
        const float p0 = __expf(s0 - mnew);
        const float p1 = __expf(s1 - mnew);
        float ls = p0 + p1;
#pragma unroll
        for (int off = 16; off > 0; off >>= 1) ls += __shfl_xor_sync(0xffffffffu, ls, off);
        li = li * alpha + ls;
        acc.x *= alpha; acc.y *= alpha; acc.z *= alpha; acc.w *= alpha;

        // accumulate P @ V
#pragma unroll
        for (int kk = 0; kk < 64; kk++) {
            const float pk = (kk < 32) ? __shfl_sync(0xffffffffu, p0, kk)
                                       : __shfl_sync(0xffffffffu, p1, kk - 32);
            float4 vv = vs4[kk * 32 + lane];
            acc.x += pk * vv.x; acc.y += pk * vv.y;
            acc.z += pk * vv.z; acc.w += pk * vv.w;
        }
        mi = mnew;
        __syncthreads();
    }

    const float inv = 1.0f / li;
    float4 r = {acc.x * inv, acc.y * inv, acc.z * inv, acc.w * inv};
    *(float4*)(o + ((size_t)(b * T_ + m) * H_ + h) * HD_ + lane * 4) = r;
}

// ---------------------------------------------------------------------------
extern "C" void kernel_launch(void* const* d_in, const int* in_sizes, int n_in,
                              void* d_out, int out_size) {
    const float* x       = (const float*)d_in[0];
    const float* Wq      = (const float*)d_in[1];
    const float* Wk      = (const float*)d_in[2];
    const float* Wv      = (const float*)d_in[3];
    const float* Wo      = (const float*)d_in[4];
    const float* q_scale = (const float*)d_in[5];
    const float* k_scale = (const float*)d_in[6];
    const float* cosT    = (const float*)d_in[7];
    const float* sinT    = (const float*)d_in[8];
    // d_in[9] = mask (bool causal) — structure is known, unused.
    float* out = (float*)d_out;

    float *q, *k, *v, *ao;
    cudaGetSymbolAddress((void**)&q,  g_q);
    cudaGetSymbolAddress((void**)&k,  g_k);
    cudaGetSymbolAddress((void**)&v,  g_v);
    cudaGetSymbolAddress((void**)&ao, g_o);

    const int M = B_ * T_;  // 4096

    // QKV projections
    sgemm128<<<dim3((H_ * HD_) / 128, M / 128), 256>>>(x, Wq, q, M, H_ * HD_, D_);
    sgemm128<<<dim3((KV_ * HD_) / 128, M / 128), 256>>>(x, Wk, k, M, KV_ * HD_, D_);
    sgemm128<<<dim3((KV_ * HD_) / 128, M / 128), 256>>>(x, Wv, v, M, KV_ * HD_, D_);

    // RMSNorm + RoPE on q and k (in place)
    rmsnorm_rope_kernel<<<(M * H_) / 8, 256>>>(q, q_scale, cosT, sinT, H_, M * H_);
    rmsnorm_rope_kernel<<<(M * KV_) / 8, 256>>>(k, k_scale, cosT, sinT, KV_, M * KV_);

    // Flash attention
    cudaFuncSetAttribute(flash_kernel, cudaFuncAttributeMaxDynamicSharedMemorySize, 65536);
    flash_kernel<<<dim3(T_ / 8, B_ * H_), 256, 65536>>>(q, k, v, ao);

    // Output projection
    sgemm128<<<dim3(D_ / 128, M / 128), 256>>>(ao, Wo, out, M, D_, H_ * HD_);
}

// round 2
// speedup vs baseline: 1.3780x; 1.3780x over previous
#include <cuda_runtime.h>
#include <math.h>

#define B_  2
#define T_  2048
#define D_  2048
#define H_  16
#define KV_ 4
#define HD_ 128

// Scratch (allocation-free rule: __device__ globals)
__device__ float g_q[(size_t)B_ * T_ * H_  * HD_];   // 32 MB
__device__ float g_k[(size_t)B_ * T_ * KV_ * HD_];   //  8 MB
__device__ float g_v[(size_t)B_ * T_ * KV_ * HD_];   //  8 MB
__device__ float g_o[(size_t)B_ * T_ * H_  * HD_];   // 32 MB

__device__ __forceinline__ unsigned f2tf(float x) {
    unsigned r;
    asm("cvt.rna.tf32.f32 %0, %1;" : "=r"(r) : "f"(x));
    return r;
}

#define MMA_TF32(cc, aa, bb)                                                   \
    asm volatile(                                                              \
        "mma.sync.aligned.m16n8k8.row.col.f32.tf32.tf32.f32 "                  \
        "{%0,%1,%2,%3}, {%4,%5,%6,%7}, {%8,%9}, {%0,%1,%2,%3};"                \
        : "+f"(cc[0]), "+f"(cc[1]), "+f"(cc[2]), "+f"(cc[3])                   \
        : "r"(aa[0]), "r"(aa[1]), "r"(aa[2]), "r"(aa[3]), "r"(bb[0]), "r"(bb[1]))

// ---------------------------------------------------------------------------
// TF32 tensor-core GEMM: C[M,N] = A[M,K] @ B[K,N], row-major fp32 in/out.
// Block tile 128x128, K-tile 32, 256 threads = 8 warps (2M x 4N), warp tile
// 64x32 via m16n8k8. Double-buffered smem (reg-staged global loads), TF32
// conversion at smem-store time. A pad 36, B pad 136 (conflict-free frags).
// ---------------------------------------------------------------------------
#define AS_STRIDE 36
#define BS_STRIDE 136
#define GEMM_SMEM (2 * (128 * AS_STRIDE + 32 * BS_STRIDE) * 4)

__global__ __launch_bounds__(256) void gemm_tf32(const float* __restrict__ A,
                                                 const float* __restrict__ B,
                                                 float* __restrict__ C,
                                                 int M, int N, int K) {
    extern __shared__ unsigned sm_u[];
    unsigned* As = sm_u;                               // [2][128*36]
    unsigned* Bs = sm_u + 2 * 128 * AS_STRIDE;         // [2][32*136]

    const int tid  = threadIdx.x;
    const int lane = tid & 31;
    const int warp = tid >> 5;
    const int wm = (warp >> 2) * 64;
    const int wn = (warp & 3) * 32;
    const int bm = blockIdx.y * 128;
    const int bn = blockIdx.x * 128;

    // global loaders: A tile 128x32 (4 float4/thr), B tile 32x128 (4 float4/thr)
    const int ar = tid >> 3;            // rows ar, ar+32, ar+64, ar+96
    const int ac = (tid & 7) * 4;
    const int br = tid >> 5;            // rows br, br+8, br+16, br+24
    const int bc = (tid & 31) * 4;

    const float* Ag = A + (size_t)(bm + ar) * K + ac;
    const float* Bg = B + (size_t)br * N + bn + bc;

    float4 areg[4], breg[4];
#pragma unroll
    for (int i = 0; i < 4; i++) areg[i] = *(const float4*)(Ag + (size_t)(i * 32) * K);
#pragma unroll
    for (int i = 0; i < 4; i++) breg[i] = *(const float4*)(Bg + (size_t)(i * 8) * N);

    float c[4][4][4];
#pragma unroll
    for (int mt = 0; mt < 4; mt++)
#pragma unroll
        for (int nt = 0; nt < 4; nt++)
#pragma unroll
            for (int i = 0; i < 4; i++) c[mt][nt][i] = 0.f;

    // store tile 0 into buffer 0 (cvt to tf32)
#pragma unroll
    for (int i = 0; i < 4; i++) {
        unsigned* p = &As[(ar + i * 32) * AS_STRIDE + ac];
        p[0] = f2tf(areg[i].x); p[1] = f2tf(areg[i].y);
        p[2] = f2tf(areg[i].z); p[3] = f2tf(areg[i].w);
    }
#pragma unroll
    for (int i = 0; i < 4; i++) {
        unsigned* p = &Bs[(br + i * 8) * BS_STRIDE + bc];
        p[0] = f2tf(breg[i].x); p[1] = f2tf(breg[i].y);
        p[2] = f2tf(breg[i].z); p[3] = f2tf(breg[i].w);
    }
    __syncthreads();

    int buf = 0;
    for (int k0 = 32; k0 <= K; k0 += 32) {
        const int nbuf = buf ^ 1;
        const bool more = (k0 < K);
        if (more) {
#pragma unroll
            for (int i = 0; i < 4; i++)
                areg[i] = *(const float4*)(Ag + (size_t)(i * 32) * K + k0);
#pragma unroll
            for (int i = 0; i < 4; i++)
                breg[i] = *(const float4*)(Bg + (size_t)(k0 + i * 8) * N);
        }

        const unsigned* Ab = As + buf * 128 * AS_STRIDE;
        const unsigned* Bb = Bs + buf * 32 * BS_STRIDE;
#pragma unroll
        for (int ks = 0; ks < 4; ks++) {
            const int kk = ks * 8;
            unsigned a[4][4], b[4][2];
#pragma unroll
            for (int mt = 0; mt < 4; mt++) {
                const unsigned* ap = Ab + (wm + mt * 16 + (lane >> 2)) * AS_STRIDE + kk + (lane & 3);
                a[mt][0] = ap[0];
                a[mt][1] = ap[8 * AS_STRIDE];
                a[mt][2] = ap[4];
                a[mt][3] = ap[8 * AS_STRIDE + 4];
            }
#pragma unroll
            for (int nt = 0; nt < 4; nt++) {
                const unsigned* bp = Bb + (kk + (lane & 3)) * BS_STRIDE + wn + nt * 8 + (lane >> 2);
                b[nt][0] = bp[0];
                b[nt][1] = bp[4 * BS_STRIDE];
            }
#pragma unroll
            for (int mt = 0; mt < 4; mt++)
#pragma unroll
                for (int nt = 0; nt < 4; nt++)
                    MMA_TF32(c[mt][nt], a[mt], b[nt]);
        }

        if (more) {
            unsigned* An = As + nbuf * 128 * AS_STRIDE;
            unsigned* Bn = Bs + nbuf * 32 * BS_STRIDE;
#pragma unroll
            for (int i = 0; i < 4; i++) {
                unsigned* p = &An[(ar + i * 32) * AS_STRIDE + ac];
                p[0] = f2tf(areg[i].x); p[1] = f2tf(areg[i].y);
                p[2] = f2tf(areg[i].z); p[3] = f2tf(areg[i].w);
            }
#pragma unroll
            for (int i = 0; i < 4; i++) {
                unsigned* p = &Bn[(br + i * 8) * BS_STRIDE + bc];
                p[0] = f2tf(breg[i].x); p[1] = f2tf(breg[i].y);
                p[2] = f2tf(breg[i].z); p[3] = f2tf(breg[i].w);
            }
        }
        __syncthreads();
        buf = nbuf;
    }

    // epilogue
#pragma unroll
    for (int mt = 0; mt < 4; mt++) {
#pragma unroll
        for (int nt = 0; nt < 4; nt++) {
            const int r0 = bm + wm + mt * 16 + (lane >> 2);
            const int cc = bn + wn + nt * 8 + (lane & 3) * 2;
            float2 v0 = {c[mt][nt][0], c[mt][nt][1]};
            float2 v1 = {c[mt][nt][2], c[mt][nt][3]};
            *(float2*)(C + (size_t)r0 * N + cc) = v0;
            *(float2*)(C + (size_t)(r0 + 8) * N + cc) = v1;
        }
    }
}

// ---------------------------------------------------------------------------
// Fused RMSNorm (over HD=128) + interleaved-pair RoPE, in place.
// ---------------------------------------------------------------------------
__global__ __launch_bounds__(256) void rmsnorm_rope_kernel(float* __restrict__ data,
                                                           const float* __restrict__ scale,
                                                           const float* __restrict__ cosT,
                                                           const float* __restrict__ sinT,
                                                           int nheads, int total_rows) {
    const int warp = threadIdx.x >> 5;
    const int lane = threadIdx.x & 31;
    const int row = blockIdx.x * 8 + warp;
    if (row >= total_rows) return;
    const int t = (row / nheads) % T_;

    float4* p = (float4*)(data + (size_t)row * HD_);
    float4 x = p[lane];
    float ss = x.x * x.x + x.y * x.y + x.z * x.z + x.w * x.w;
#pragma unroll
    for (int o = 16; o > 0; o >>= 1) ss += __shfl_xor_sync(0xffffffffu, ss, o);
    const float rinv = rsqrtf(ss * (1.0f / HD_) + 1e-6f);

    const int d0 = lane * 4;
    float4 sc = *(const float4*)(scale + d0);
    float n0 = x.x * rinv * sc.x;
    float n1 = x.y * rinv * sc.y;
    float n2 = x.z * rinv * sc.z;
    float n3 = x.w * rinv * sc.w;

    const float c0 = cosT[(size_t)t * HD_ + d0];
    const float s0 = sinT[(size_t)t * HD_ + d0];
    const float c1 = cosT[(size_t)t * HD_ + d0 + 2];
    const float s1 = sinT[(size_t)t * HD_ + d0 + 2];

    float4 r;
    r.x = n0 * c0 - n1 * s0;
    r.y = n1 * c0 + n0 * s0;
    r.z = n2 * c1 - n3 * s1;
    r.w = n3 * c1 + n2 * s1;
    p[lane] = r;
}

// ---------------------------------------------------------------------------
// Causal GQA flash attention (fp32, online softmax).
// Block = 256 threads = 8 warps; each warp owns 1 query row.
// ---------------------------------------------------------------------------
__global__ __launch_bounds__(256) void flash_kernel(const float* __restrict__ q,
                                                    const float* __restrict__ k,
                                                    const float* __restrict__ v,
                                                    float* __restrict__ o) {
    extern __shared__ float sm[];
    float4* ks4 = (float4*)sm;                 // [64][32] float4
    float4* vs4 = (float4*)(sm + 64 * HD_);    // [64][32] float4

    const int tid = threadIdx.x;
    const int warp = tid >> 5;
    const int lane = tid & 31;
    const int bh = blockIdx.y;
    const int b = bh / H_;
    const int h = bh - b * H_;
    const int g = h / (H_ / KV_);
    const int m = blockIdx.x * 8 + warp;

    const float sscale = 0.08838834764831845f;  // 1/sqrt(128)
    float4 qv = *(const float4*)(q + ((size_t)(b * T_ + m) * H_ + h) * HD_ + lane * 4);
    qv.x *= sscale; qv.y *= sscale; qv.z *= sscale; qv.w *= sscale;

    float mi = -1e30f, li = 0.f;
    float4 acc = {0.f, 0.f, 0.f, 0.f};

    const int ntiles = (blockIdx.x * 8 + 7) / 64 + 1;
    for (int j = 0; j < ntiles; j++) {
        const int base = j * 64;
        for (int it = tid; it < 64 * 32; it += 256) {
            const int r = it >> 5, c = it & 31;
            const size_t gi = ((size_t)(b * T_ + base + r) * KV_ + g) * HD_ + c * 4;
            ks4[it] = *(const float4*)(k + gi);
            vs4[it] = *(const float4*)(v + gi);
        }
        __syncthreads();

        float s0 = -1e30f, s1 = -1e30f;
#pragma unroll
        for (int kk = 0; kk < 64; kk++) {
            float4 kv = ks4[kk * 32 + lane];
            float p = qv.x * kv.x + qv.y * kv.y + qv.z * kv.z + qv.w * kv.w;
#pragma unroll
            for (int off = 16; off > 0; off >>= 1) p += __shfl_xor_sync(0xffffffffu, p, off);
            const float sv = (base + kk <= m) ? p : -1e30f;
            if ((kk & 31) == lane) {
                if (kk < 32) s0 = sv; else s1 = sv;
            }
        }

        float tmax = fmaxf(s0, s1);
#pragma unroll
        for (int off = 16; off > 0; off >>= 1)
            tmax = fmaxf(tmax, __shfl_xor_sync(0xffffffffu, tmax, off));
        const float mnew = fmaxf(mi, tmax);
        const float alpha = __expf(mi - mnew);
        const float p0 = __expf(s0 - mnew);
        const float p1 = __expf(s1 - mnew);
        float ls = p0 + p1;
#pragma unroll
        for (int off = 16; off > 0; off >>= 1) ls += __shfl_xor_sync(0xffffffffu, ls, off);
        li = li * alpha + ls;
        acc.x *= alpha; acc.y *= alpha; acc.z *= alpha; acc.w *= alpha;

#pragma unroll
        for (int kk = 0; kk < 64; kk++) {
            const float pk = (kk < 32) ? __shfl_sync(0xffffffffu, p0, kk)
                                       : __shfl_sync(0xffffffffu, p1, kk - 32);
            float4 vv = vs4[kk * 32 + lane];
            acc.x += pk * vv.x; acc.y += pk * vv.y;
            acc.z += pk * vv.z; acc.w += pk * vv.w;
        }
        mi = mnew;
        __syncthreads();
    }

    const float inv = 1.0f / li;
    float4 r = {acc.x * inv, acc.y * inv, acc.z * inv, acc.w * inv};
    *(float4*)(o + ((size_t)(b * T_ + m) * H_ + h) * HD_ + lane * 4) = r;
}

// ---------------------------------------------------------------------------
extern "C" void kernel_launch(void* const* d_in, const int* in_sizes, int n_in,
                              void* d_out, int out_size) {
    const float* x       = (const float*)d_in[0];
    const float* Wq      = (const float*)d_in[1];
    const float* Wk      = (const float*)d_in[2];
    const float* Wv      = (const float*)d_in[3];
    const float* Wo      = (const float*)d_in[4];
    const float* q_scale = (const float*)d_in[5];
    const float* k_scale = (const float*)d_in[6];
    const float* cosT    = (const float*)d_in[7];
    const float* sinT    = (const float*)d_in[8];
    float* out = (float*)d_out;

    float *q, *k, *v, *ao;
    cudaGetSymbolAddress((void**)&q,  g_q);
    cudaGetSymbolAddress((void**)&k,  g_k);
    cudaGetSymbolAddress((void**)&v,  g_v);
    cudaGetSymbolAddress((void**)&ao, g_o);

    const int M = B_ * T_;  // 4096

    cudaFuncSetAttribute(gemm_tf32, cudaFuncAttributeMaxDynamicSharedMemorySize, GEMM_SMEM);

    // QKV projections (TF32 tensor cores)
    gemm_tf32<<<dim3((H_ * HD_) / 128, M / 128), 256, GEMM_SMEM>>>(x, Wq, q, M, H_ * HD_, D_);
    gemm_tf32<<<dim3((KV_ * HD_) / 128, M / 128), 256, GEMM_SMEM>>>(x, Wk, k, M, KV_ * HD_, D_);
    gemm_tf32<<<dim3((KV_ * HD_) / 128, M / 128), 256, GEMM_SMEM>>>(x, Wv, v, M, KV_ * HD_, D_);

    // RMSNorm + RoPE on q and k (in place)
    rmsnorm_rope_kernel<<<(M * H_) / 8, 256>>>(q, q_scale, cosT, sinT, H_, M * H_);
    rmsnorm_rope_kernel<<<(M * KV_) / 8, 256>>>(k, k_scale, cosT, sinT, KV_, M * KV_);

    // Flash attention
    cudaFuncSetAttribute(flash_kernel, cudaFuncAttributeMaxDynamicSharedMemorySize, 65536);
    flash_kernel<<<dim3(T_ / 8, B_ * H_), 256, 65536>>>(q, k, v, ao);

    // Output projection (TF32 tensor cores)
    gemm_tf32<<<dim3(D_ / 128, M / 128), 256, GEMM_SMEM>>>(ao, Wo, out, M, D_, H_ * HD_);
}

// round 4
// speedup vs baseline: 5.1449x; 3.7336x over previous
#include <cuda_runtime.h>
#include <math.h>

#define B_  2
#define T_  2048
#define D_  2048
#define H_  16
#define KV_ 4
#define HD_ 128

// Scratch (allocation-free rule: __device__ globals)
__device__ float g_q[(size_t)B_ * T_ * H_  * HD_];   // 32 MB
__device__ float g_k[(size_t)B_ * T_ * KV_ * HD_];   //  8 MB
__device__ float g_v[(size_t)B_ * T_ * KV_ * HD_];   //  8 MB
__device__ float g_o[(size_t)B_ * T_ * H_  * HD_];   // 32 MB

__device__ __forceinline__ unsigned f2tf(float x) {
    unsigned r;
    asm("cvt.rna.tf32.f32 %0, %1;" : "=r"(r) : "f"(x));
    return r;
}

#define MMA_TF32(cc, aa, bb)                                                   \
    asm volatile(                                                              \
        "mma.sync.aligned.m16n8k8.row.col.f32.tf32.tf32.f32 "                  \
        "{%0,%1,%2,%3}, {%4,%5,%6,%7}, {%8,%9}, {%0,%1,%2,%3};"                \
        : "+f"(cc[0]), "+f"(cc[1]), "+f"(cc[2]), "+f"(cc[3])                   \
        : "r"(aa[0]), "r"(aa[1]), "r"(aa[2]), "r"(aa[3]), "r"(bb[0]), "r"(bb[1]))

// ---------------------------------------------------------------------------
// TF32 tensor-core GEMM: C[M,N] = A[M,K] @ B[K,N], row-major fp32 in/out.
// Block tile 128x128, K-tile 32, 8 warps (2Mx4N), warp tile 64x32, m16n8k8.
// Double-buffered smem, reg-staged global loads, tf32 cvt at smem-store.
// ---------------------------------------------------------------------------
#define AS_STRIDE 36
#define BS_STRIDE 136
#define GEMM_SMEM (2 * (128 * AS_STRIDE + 32 * BS_STRIDE) * 4)

__global__ __launch_bounds__(256) void gemm_tf32(const float* __restrict__ A,
                                                 const float* __restrict__ B,
                                                 float* __restrict__ C,
                                                 int M, int N, int K) {
    extern __shared__ unsigned sm_u[];
    unsigned* As = sm_u;
    unsigned* Bs = sm_u + 2 * 128 * AS_STRIDE;

    const int tid  = threadIdx.x;
    const int lane = tid & 31;
    const int warp = tid >> 5;
    const int wm = (warp >> 2) * 64;
    const int wn = (warp & 3) * 32;
    const int bm = blockIdx.y * 128;
    const int bn = blockIdx.x * 128;

    const int ar = tid >> 3;
    const int ac = (tid & 7) * 4;
    const int br = tid >> 5;
    const int bc = (tid & 31) * 4;

    const float* Ag = A + (size_t)(bm + ar) * K + ac;
    const float* Bg = B + (size_t)br * N + bn + bc;

    float4 areg[4], breg[4];
#pragma unroll
    for (int i = 0; i < 4; i++) areg[i] = *(const float4*)(Ag + (size_t)(i * 32) * K);
#pragma unroll
    for (int i = 0; i < 4; i++) breg[i] = *(const float4*)(Bg + (size_t)(i * 8) * N);

    float c[4][4][4];
#pragma unroll
    for (int mt = 0; mt < 4; mt++)
#pragma unroll
        for (int nt = 0; nt < 4; nt++)
#pragma unroll
            for (int i = 0; i < 4; i++) c[mt][nt][i] = 0.f;

#pragma unroll
    for (int i = 0; i < 4; i++) {
        unsigned* p = &As[(ar + i * 32) * AS_STRIDE + ac];
        p[0] = f2tf(areg[i].x); p[1] = f2tf(areg[i].y);
        p[2] = f2tf(areg[i].z); p[3] = f2tf(areg[i].w);
    }
#pragma unroll
    for (int i = 0; i < 4; i++) {
        unsigned* p = &Bs[(br + i * 8) * BS_STRIDE + bc];
        p[0] = f2tf(breg[i].x); p[1] = f2tf(breg[i].y);
        p[2] = f2tf(breg[i].z); p[3] = f2tf(breg[i].w);
    }
    __syncthreads();

    int buf = 0;
    for (int k0 = 32; k0 <= K; k0 += 32) {
        const int nbuf = buf ^ 1;
        const bool more = (k0 < K);
        if (more) {
#pragma unroll
            for (int i = 0; i < 4; i++)
                areg[i] = *(const float4*)(Ag + (size_t)(i * 32) * K + k0);
#pragma unroll
            for (int i = 0; i < 4; i++)
                breg[i] = *(const float4*)(Bg + (size_t)(k0 + i * 8) * N);
        }

        const unsigned* Ab = As + buf * 128 * AS_STRIDE;
        const unsigned* Bb = Bs + buf * 32 * BS_STRIDE;
#pragma unroll
        for (int ks = 0; ks < 4; ks++) {
            const int kk = ks * 8;
            unsigned a[4][4], b[4][2];
#pragma unroll
            for (int mt = 0; mt < 4; mt++) {
                const unsigned* ap = Ab + (wm + mt * 16 + (lane >> 2)) * AS_STRIDE + kk + (lane & 3);
                a[mt][0] = ap[0];
                a[mt][1] = ap[8 * AS_STRIDE];
                a[mt][2] = ap[4];
                a[mt][3] = ap[8 * AS_STRIDE + 4];
            }
#pragma unroll
            for (int nt = 0; nt < 4; nt++) {
                const unsigned* bp = Bb + (kk + (lane & 3)) * BS_STRIDE + wn + nt * 8 + (lane >> 2);
                b[nt][0] = bp[0];
                b[nt][1] = bp[4 * BS_STRIDE];
            }
#pragma unroll
            for (int mt = 0; mt < 4; mt++)
#pragma unroll
                for (int nt = 0; nt < 4; nt++)
                    MMA_TF32(c[mt][nt], a[mt], b[nt]);
        }

        if (more) {
            unsigned* An = As + nbuf * 128 * AS_STRIDE;
            unsigned* Bn = Bs + nbuf * 32 * BS_STRIDE;
#pragma unroll
            for (int i = 0; i < 4; i++) {
                unsigned* p = &An[(ar + i * 32) * AS_STRIDE + ac];
                p[0] = f2tf(areg[i].x); p[1] = f2tf(areg[i].y);
                p[2] = f2tf(areg[i].z); p[3] = f2tf(areg[i].w);
            }
#pragma unroll
            for (int i = 0; i < 4; i++) {
                unsigned* p = &Bn[(br + i * 8) * BS_STRIDE + bc];
                p[0] = f2tf(breg[i].x); p[1] = f2tf(breg[i].y);
                p[2] = f2tf(breg[i].z); p[3] = f2tf(breg[i].w);
            }
        }
        __syncthreads();
        buf = nbuf;
    }

#pragma unroll
    for (int mt = 0; mt < 4; mt++) {
#pragma unroll
        for (int nt = 0; nt < 4; nt++) {
            const int r0 = bm + wm + mt * 16 + (lane >> 2);
            const int cc = bn + wn + nt * 8 + (lane & 3) * 2;
            float2 v0 = {c[mt][nt][0], c[mt][nt][1]};
            float2 v1 = {c[mt][nt][2], c[mt][nt][3]};
            *(float2*)(C + (size_t)r0 * N + cc) = v0;
            *(float2*)(C + (size_t)(r0 + 8) * N + cc) = v1;
        }
    }
}

// ---------------------------------------------------------------------------
// Fused RMSNorm (over HD=128) + interleaved-pair RoPE, in place.
// ---------------------------------------------------------------------------
__global__ __launch_bounds__(256) void rmsnorm_rope_kernel(float* __restrict__ data,
                                                           const float* __restrict__ scale,
                                                           const float* __restrict__ cosT,
                                                           const float* __restrict__ sinT,
                                                           int nheads, int total_rows) {
    const int warp = threadIdx.x >> 5;
    const int lane = threadIdx.x & 31;
    const int row = blockIdx.x * 8 + warp;
    if (row >= total_rows) return;
    const int t = (row / nheads) % T_;

    float4* p = (float4*)(data + (size_t)row * HD_);
    float4 x = p[lane];
    float ss = x.x * x.x + x.y * x.y + x.z * x.z + x.w * x.w;
#pragma unroll
    for (int o = 16; o > 0; o >>= 1) ss += __shfl_xor_sync(0xffffffffu, ss, o);
    const float rinv = rsqrtf(ss * (1.0f / HD_) + 1e-6f);

    const int d0 = lane * 4;
    float4 sc = *(const float4*)(scale + d0);
    float n0 = x.x * rinv * sc.x;
    float n1 = x.y * rinv * sc.y;
    float n2 = x.z * rinv * sc.z;
    float n3 = x.w * rinv * sc.w;

    const float c0 = cosT[(size_t)t * HD_ + d0];
    const float s0 = sinT[(size_t)t * HD_ + d0];
    const float c1 = cosT[(size_t)t * HD_ + d0 + 2];
    const float s1 = sinT[(size_t)t * HD_ + d0 + 2];

    float4 r;
    r.x = n0 * c0 - n1 * s0;
    r.y = n1 * c0 + n0 * s0;
    r.z = n2 * c1 - n3 * s1;
    r.w = n3 * c1 + n2 * s1;
    p[lane] = r;
}

// ---------------------------------------------------------------------------
// Tensor-core causal GQA flash attention (TF32 mma, online softmax).
// Block: 256 thr = 8 warps; 128 query rows/block (16 per warp), 64-key tiles.
// Softmax is warp-local. P re-shaped c->a frags via per-warp smem buffer.
// grid = (T/128, B*H); heavy q-tiles launched first.
// ---------------------------------------------------------------------------
#define FA_PAD  132   // row stride (u32) for Qs/Ks/Vs
#define FA_PPAD 68    // row stride (u32) for per-warp P buffer
#define FA_SMEM ((128 * FA_PAD + 64 * FA_PAD + 64 * FA_PAD + 8 * 16 * FA_PPAD) * 4)

__global__ __launch_bounds__(256, 1) void flash_tc(const float* __restrict__ q,
                                                   const float* __restrict__ k,
                                                   const float* __restrict__ v,
                                                   float* __restrict__ o) {
    extern __shared__ unsigned fsm[];
    unsigned* Qs = fsm;
    unsigned* Ks = Qs + 128 * FA_PAD;
    unsigned* Vs = Ks + 64 * FA_PAD;
    unsigned* Psw = Vs + 64 * FA_PAD + (threadIdx.x >> 5) * 16 * FA_PPAD;

    const int tid  = threadIdx.x;
    const int warp = tid >> 5;
    const int lane = tid & 31;
    const int la3  = lane & 3;
    const int r    = lane >> 2;
    const int bh = blockIdx.y;
    const int b = bh >> 4;          // H_=16
    const int h = bh & 15;
    const int g = h >> 2;           // H_/KV_ = 4
    const int qb = (gridDim.x - 1) - blockIdx.x;   // heavy tiles first
    const int qbase = qb * 128;
    const int wm = warp * 16;

    const float sscale = 0.08838834764831845f;  // 1/sqrt(128)

    // Load Q tile (128 x 128), fold in score scale, cvt tf32
    for (int i = tid; i < 128 * 32; i += 256) {
        const int row = i >> 5, c4 = (i & 31) * 4;
        float4 t = *(const float4*)(q + ((size_t)(b * T_ + qbase + row) * H_ + h) * HD_ + c4);
        uint4 u = {f2tf(t.x * sscale), f2tf(t.y * sscale), f2tf(t.z * sscale), f2tf(t.w * sscale)};
        *(uint4*)&Qs[row * FA_PAD + c4] = u;
    }
    __syncthreads();

    float m0 = -1e30f, m1 = -1e30f, l0 = 0.f, l1 = 0.f;
    float acc[16][4];
#pragma unroll
    for (int ns = 0; ns < 16; ns++)
#pragma unroll
        for (int i = 0; i < 4; i++) acc[ns][i] = 0.f;

    const int row0 = qbase + wm + r;   // global q row for c-frag row 0
    const int ntiles = (qb + 1) * 2;

    for (int j = 0; j < ntiles; j++) {
        const int kbase = j * 64;
        // Load K,V tile (64 x 128 each)
        for (int i = tid; i < 64 * 32; i += 256) {
            const int row = i >> 5, c4 = (i & 31) * 4;
            const size_t gi = ((size_t)(b * T_ + kbase + row) * KV_ + g) * HD_ + c4;
            float4 kt = *(const float4*)(k + gi);
            float4 vt = *(const float4*)(v + gi);
            uint4 ku = {f2tf(kt.x), f2tf(kt.y), f2tf(kt.z), f2tf(kt.w)};
            uint4 vu = {f2tf(vt.x), f2tf(vt.y), f2tf(vt.z), f2tf(vt.w)};
            *(uint4*)&Ks[row * FA_PAD + c4] = ku;
            *(uint4*)&Vs[row * FA_PAD + c4] = vu;
        }
        __syncthreads();

        const bool active = (kbase <= qbase + wm + 15);
        if (active) {
            // S = Q . K^T  (16 x 64 per warp)
            float s[8][4];
#pragma unroll
            for (int ns = 0; ns < 8; ns++)
#pragma unroll
                for (int i = 0; i < 4; i++) s[ns][i] = 0.f;

#pragma unroll
            for (int kc = 0; kc < 16; kc++) {
                unsigned a[4];
                const unsigned* ap = Qs + (wm + r) * FA_PAD + kc * 8 + la3;
                a[0] = ap[0];
                a[1] = ap[8 * FA_PAD];
                a[2] = ap[4];
                a[3] = ap[8 * FA_PAD + 4];
#pragma unroll
                for (int ns = 0; ns < 8; ns++) {
                    unsigned bf[2];
                    const unsigned* bp = Ks + (ns * 8 + r) * FA_PAD + kc * 8 + la3;
                    bf[0] = bp[0];
                    bf[1] = bp[4];
                    MMA_TF32(s[ns], a, bf);
                }
            }

            // causal mask
            if (kbase + 63 > qbase + wm) {
#pragma unroll
                for (int ns = 0; ns < 8; ns++) {
                    const int col = kbase + ns * 8 + la3 * 2;
                    if (col > row0)     s[ns][0] = -1e30f;
                    if (col + 1 > row0) s[ns][1] = -1e30f;
                    if (col > row0 + 8)     s[ns][2] = -1e30f;
                    if (col + 1 > row0 + 8) s[ns][3] = -1e30f;
                }
            }

            // row max (within thread, then across quad)
            float mx0 = -1e30f, mx1 = -1e30f;
#pragma unroll
            for (int ns = 0; ns < 8; ns++) {
                mx0 = fmaxf(mx0, fmaxf(s[ns][0], s[ns][1]));
                mx1 = fmaxf(mx1, fmaxf(s[ns][2], s[ns][3]));
            }
            mx0 = fmaxf(mx0, __shfl_xor_sync(0xffffffffu, mx0, 1));
            mx0 = fmaxf(mx0, __shfl_xor_sync(0xffffffffu, mx0, 2));
            mx1 = fmaxf(mx1, __shfl_xor_sync(0xffffffffu, mx1, 1));
            mx1 = fmaxf(mx1, __shfl_xor_sync(0xffffffffu, mx1, 2));

            const float mn0 = fmaxf(m0, mx0);
            const float mn1 = fmaxf(m1, mx1);
            const float al0 = __expf(m0 - mn0);
            const float al1 = __expf(m1 - mn1);
            m0 = mn0; m1 = mn1;

            // exp + row sums + stash P (tf32) in per-warp buffer
            float sum0 = 0.f, sum1 = 0.f;
#pragma unroll
            for (int ns = 0; ns < 8; ns++) {
                float p0 = __expf(s[ns][0] - mn0);
                float p1 = __expf(s[ns][1] - mn0);
                float p2 = __expf(s[ns][2] - mn1);
                float p3 = __expf(s[ns][3] - mn1);
                sum0 += p0 + p1;
                sum1 += p2 + p3;
                uint2 u0 = {f2tf(p0), f2tf(p1)};
                uint2 u1 = {f2tf(p2), f2tf(p3)};
                *(uint2*)&Psw[r * FA_PPAD + ns * 8 + la3 * 2] = u0;
                *(uint2*)&Psw[(r + 8) * FA_PPAD + ns * 8 + la3 * 2] = u1;
            }
            sum0 += __shfl_xor_sync(0xffffffffu, sum0, 1);
            sum0 += __shfl_xor_sync(0xffffffffu, sum0, 2);
            sum1 += __shfl_xor_sync(0xffffffffu, sum1, 1);
            sum1 += __shfl_xor_sync(0xffffffffu, sum1, 2);
            l0 = l0 * al0 + sum0;
            l1 = l1 * al1 + sum1;

            // rescale accumulators
#pragma unroll
            for (int ns = 0; ns < 16; ns++) {
                acc[ns][0] *= al0; acc[ns][1] *= al0;
                acc[ns][2] *= al1; acc[ns][3] *= al1;
            }
            __syncwarp();

            // O += P . V   (P: 16x64, V: 64x128)
#pragma unroll
            for (int kc = 0; kc < 8; kc++) {
                unsigned a[4];
                const unsigned* ap = Psw + r * FA_PPAD + kc * 8 + la3;
                a[0] = ap[0];
                a[1] = ap[8 * FA_PPAD];
                a[2] = ap[4];
                a[3] = ap[8 * FA_PPAD + 4];
#pragma unroll
                for (int ns = 0; ns < 16; ns++) {
                    unsigned bf[2];
                    const unsigned* bp = Vs + (kc * 8 + la3) * FA_PAD + ns * 8 + r;
                    bf[0] = bp[0];
                    bf[1] = bp[4 * FA_PAD];
                    MMA_TF32(acc[ns], a, bf);
                }
            }
        }
        __syncthreads();
    }

    // epilogue
    const float inv0 = 1.0f / l0;
    const float inv1 = 1.0f / l1;
    float* o0 = o + ((size_t)(b * T_ + row0) * H_ + h) * HD_;
    float* o1 = o + ((size_t)(b * T_ + row0 + 8) * H_ + h) * HD_;
#pragma unroll
    for (int ns = 0; ns < 16; ns++) {
        const int col = ns * 8 + la3 * 2;
        float2 v0 = {acc[ns][0] * inv0, acc[ns][1] * inv0};
        float2 v1 = {acc[ns][2] * inv1, acc[ns][3] * inv1};
        *(float2*)(o0 + col) = v0;
        *(float2*)(o1 + col) = v1;
    }
}

// ---------------------------------------------------------------------------
extern "C" void kernel_launch(void* const* d_in, const int* in_sizes, int n_in,
                              void* d_out, int out_size) {
    const float* x       = (const float*)d_in[0];
    const float* Wq      = (const float*)d_in[1];
    const float* Wk      = (const float*)d_in[2];
    const float* Wv      = (const float*)d_in[3];
    const float* Wo      = (const float*)d_in[4];
    const float* q_scale = (const float*)d_in[5];
    const float* k_scale = (const float*)d_in[6];
    const float* cosT    = (const float*)d_in[7];
    const float* sinT    = (const float*)d_in[8];
    float* out = (float*)d_out;

    float *q, *k, *v, *ao;
    cudaGetSymbolAddress((void**)&q,  g_q);
    cudaGetSymbolAddress((void**)&k,  g_k);
    cudaGetSymbolAddress((void**)&v,  g_v);
    cudaGetSymbolAddress((void**)&ao, g_o);

    const int M = B_ * T_;  // 4096

    cudaFuncSetAttribute(gemm_tf32, cudaFuncAttributeMaxDynamicSharedMemorySize, GEMM_SMEM);
    cudaFuncSetAttribute(flash_tc, cudaFuncAttributeMaxDynamicSharedMemorySize, FA_SMEM);

    // QKV projections (TF32 tensor cores)
    gemm_tf32<<<dim3((H_ * HD_) / 128, M / 128), 256, GEMM_SMEM>>>(x, Wq, q, M, H_ * HD_, D_);
    gemm_tf32<<<dim3((KV_ * HD_) / 128, M / 128), 256, GEMM_SMEM>>>(x, Wk, k, M, KV_ * HD_, D_);
    gemm_tf32<<<dim3((KV_ * HD_) / 128, M / 128), 256, GEMM_SMEM>>>(x, Wv, v, M, KV_ * HD_, D_);

    // RMSNorm + RoPE on q and k (in place)
    rmsnorm_rope_kernel<<<(M * H_) / 8, 256>>>(q, q_scale, cosT, sinT, H_, M * H_);
    rmsnorm_rope_kernel<<<(M * KV_) / 8, 256>>>(k, k_scale, cosT, sinT, KV_, M * KV_);

    // Tensor-core flash attention
    flash_tc<<<dim3(T_ / 128, B_ * H_), 256, FA_SMEM>>>(q, k, v, ao);

    // Output projection (TF32 tensor cores)
    gemm_tf32<<<dim3(D_ / 128, M / 128), 256, GEMM_SMEM>>>(ao, Wo, out, M, D_, H_ * HD_);
}

// round 8
// speedup vs baseline: 5.5727x; 1.0831x over previous
#include <cuda_runtime.h>
#include <math.h>

#define B_  2
#define T_  2048
#define D_  2048
#define H_  16
#define KV_ 4
#define HD_ 128

// Scratch (allocation-free rule: __device__ globals)
__device__ float g_q[(size_t)B_ * T_ * H_  * HD_];   // 32 MB
__device__ float g_k[(size_t)B_ * T_ * KV_ * HD_];   //  8 MB
__device__ float g_v[(size_t)B_ * T_ * KV_ * HD_];   //  8 MB
__device__ float g_o[(size_t)B_ * T_ * H_  * HD_];   // 32 MB

__device__ __forceinline__ unsigned f2tf(float x) {
    unsigned r;
    asm("cvt.rna.tf32.f32 %0, %1;" : "=r"(r) : "f"(x));
    return r;
}

#define MMA_TF32(cc, aa, bb)                                                   \
    asm volatile(                                                              \
        "mma.sync.aligned.m16n8k8.row.col.f32.tf32.tf32.f32 "                  \
        "{%0,%1,%2,%3}, {%4,%5,%6,%7}, {%8,%9}, {%0,%1,%2,%3};"                \
        : "+f"(cc[0]), "+f"(cc[1]), "+f"(cc[2]), "+f"(cc[3])                   \
        : "r"(aa[0]), "r"(aa[1]), "r"(aa[2]), "r"(aa[3]), "r"(bb[0]), "r"(bb[1]))

#define AS_STRIDE 36
#define BS_STRIDE 136
#define GEMM_SMEM (2 * (128 * AS_STRIDE + 32 * BS_STRIDE) * 4)

// ===========================================================================
// TF32 GEMM mainloop: 128x128 C tile into c[4][4][4] register fragments.
// A row-major [M,K], B row-major [K,N]. 8 warps (2Mx4N), warp tile 64x32,
// K-tile 32, double-buffered smem, tf32 cvt at smem-store time.
// (Identical math/layout to the R4 kernel that passed at 1237 us.)
// ===========================================================================
struct GemmFrag { float c[4][4][4]; };

__device__ __forceinline__ void gemm_mainloop(
    const float* __restrict__ A, const float* __restrict__ B,
    unsigned* As, unsigned* Bs,
    int bm, int bn, int N, int K, GemmFrag& F)
{
    const int tid  = threadIdx.x;
    const int lane = tid & 31;
    const int warp = tid >> 5;
    const int wm = (warp >> 2) * 64;
    const int wn = (warp & 3) * 32;

    const int ar = tid >> 3;
    const int ac = (tid & 7) * 4;
    const int br = tid >> 5;
    const int bc = (tid & 31) * 4;

    const float* Ag = A + (size_t)(bm + ar) * K + ac;
    const float* Bg = B + (size_t)br * N + bn + bc;

    float4 areg[4], breg[4];
#pragma unroll
    for (int i = 0; i < 4; i++) areg[i] = *(const float4*)(Ag + (size_t)(i * 32) * K);
#pragma unroll
    for (int i = 0; i < 4; i++) breg[i] = *(const float4*)(Bg + (size_t)(i * 8) * N);

#pragma unroll
    for (int mt = 0; mt < 4; mt++)
#pragma unroll
        for (int nt = 0; nt < 4; nt++)
#pragma unroll
            for (int i = 0; i < 4; i++) F.c[mt][nt][i] = 0.f;

#pragma unroll
    for (int i = 0; i < 4; i++) {
        unsigned* p = &As[(ar + i * 32) * AS_STRIDE + ac];
        p[0] = f2tf(areg[i].x); p[1] = f2tf(areg[i].y);
        p[2] = f2tf(areg[i].z); p[3] = f2tf(areg[i].w);
    }
#pragma unroll
    for (int i = 0; i < 4; i++) {
        unsigned* p = &Bs[(br + i * 8) * BS_STRIDE + bc];
        p[0] = f2tf(breg[i].x); p[1] = f2tf(breg[i].y);
        p[2] = f2tf(breg[i].z); p[3] = f2tf(breg[i].w);
    }
    __syncthreads();

    int buf = 0;
    for (int k0 = 32; k0 <= K; k0 += 32) {
        const int nbuf = buf ^ 1;
        const bool more = (k0 < K);
        if (more) {
#pragma unroll
            for (int i = 0; i < 4; i++)
                areg[i] = *(const float4*)(Ag + (size_t)(i * 32) * K + k0);
#pragma unroll
            for (int i = 0; i < 4; i++)
                breg[i] = *(const float4*)(Bg + (size_t)(k0 + i * 8) * N);
        }

        const unsigned* Ab = As + buf * 128 * AS_STRIDE;
        const unsigned* Bb = Bs + buf * 32 * BS_STRIDE;
#pragma unroll
        for (int ks = 0; ks < 4; ks++) {
            const int kk = ks * 8;
            unsigned a[4][4], b[4][2];
#pragma unroll
            for (int mt = 0; mt < 4; mt++) {
                const unsigned* ap = Ab + (wm + mt * 16 + (lane >> 2)) * AS_STRIDE + kk + (lane & 3);
                a[mt][0] = ap[0];
                a[mt][1] = ap[8 * AS_STRIDE];
                a[mt][2] = ap[4];
                a[mt][3] = ap[8 * AS_STRIDE + 4];
            }
#pragma unroll
            for (int nt = 0; nt < 4; nt++) {
                const unsigned* bp = Bb + (kk + (lane & 3)) * BS_STRIDE + wn + nt * 8 + (lane >> 2);
                b[nt][0] = bp[0];
                b[nt][1] = bp[4 * BS_STRIDE];
            }
#pragma unroll
            for (int mt = 0; mt < 4; mt++)
#pragma unroll
                for (int nt = 0; nt < 4; nt++)
                    MMA_TF32(F.c[mt][nt], a[mt], b[nt]);
        }

        if (more) {
            unsigned* An = As + nbuf * 128 * AS_STRIDE;
            unsigned* Bn = Bs + nbuf * 32 * BS_STRIDE;
#pragma unroll
            for (int i = 0; i < 4; i++) {
                unsigned* p = &An[(ar + i * 32) * AS_STRIDE + ac];
                p[0] = f2tf(areg[i].x); p[1] = f2tf(areg[i].y);
                p[2] = f2tf(areg[i].z); p[3] = f2tf(areg[i].w);
            }
#pragma unroll
            for (int i = 0; i < 4; i++) {
                unsigned* p = &Bn[(br + i * 8) * BS_STRIDE + bc];
                p[0] = f2tf(breg[i].x); p[1] = f2tf(breg[i].y);
                p[2] = f2tf(breg[i].z); p[3] = f2tf(breg[i].w);
            }
        }
        __syncthreads();
        buf = nbuf;
    }
}

__device__ __forceinline__ void gemm_store(float* __restrict__ C, int bm, int bn,
                                           int N, const GemmFrag& F) {
    const int lane = threadIdx.x & 31;
    const int warp = threadIdx.x >> 5;
    const int wm = (warp >> 2) * 64;
    const int wn = (warp & 3) * 32;
#pragma unroll
    for (int mt = 0; mt < 4; mt++)
#pragma unroll
        for (int nt = 0; nt < 4; nt++) {
            const int r0 = bm + wm + mt * 16 + (lane >> 2);
            const int cc = bn + wn + nt * 8 + (lane & 3) * 2;
            float2 v0 = {F.c[mt][nt][0], F.c[mt][nt][1]};
            float2 v1 = {F.c[mt][nt][2], F.c[mt][nt][3]};
            *(float2*)(C + (size_t)r0 * N + cc) = v0;
            *(float2*)(C + (size_t)(r0 + 8) * N + cc) = v1;
        }
}

// ===========================================================================
// Combined QKV projection GEMM (plain stores; rmsnorm/rope stay separate).
// grid.x = 768: [0,512) q-tiles, [512,640) k-tiles, [640,768) v-tiles.
// ===========================================================================
__global__ __launch_bounds__(256) void qkv_gemm(const float* __restrict__ x,
                                                const float* __restrict__ Wq,
                                                const float* __restrict__ Wk,
                                                const float* __restrict__ Wv,
                                                float* __restrict__ qo,
                                                float* __restrict__ ko,
                                                float* __restrict__ vo) {
    extern __shared__ unsigned sm_u[];
    unsigned* As = sm_u;
    unsigned* Bs = sm_u + 2 * 128 * AS_STRIDE;

    const int bx = blockIdx.x;
    int bm, bn, N;
    const float* Bmat;
    float* Cmat;
    if (bx < 512) {
        Bmat = Wq; Cmat = qo; N = H_ * HD_;
        bn = (bx & 15) * 128; bm = (bx >> 4) * 128;
    } else if (bx < 640) {
        const int l = bx - 512;
        Bmat = Wk; Cmat = ko; N = KV_ * HD_;
        bn = (l & 3) * 128; bm = (l >> 2) * 128;
    } else {
        const int l = bx - 640;
        Bmat = Wv; Cmat = vo; N = KV_ * HD_;
        bn = (l & 3) * 128; bm = (l >> 2) * 128;
    }

    GemmFrag F;
    gemm_mainloop(x, Bmat, As, Bs, bm, bn, N, D_, F);
    gemm_store(Cmat, bm, bn, N, F);
}

// ===========================================================================
// Plain TF32 GEMM (O projection).
// ===========================================================================
__global__ __launch_bounds__(256) void gemm_tf32(const float* __restrict__ A,
                                                 const float* __restrict__ B,
                                                 float* __restrict__ C,
                                                 int M, int N, int K) {
    extern __shared__ unsigned sm_u[];
    unsigned* As = sm_u;
    unsigned* Bs = sm_u + 2 * 128 * AS_STRIDE;

    const int bm = blockIdx.y * 128;
    const int bn = blockIdx.x * 128;

    GemmFrag F;
    gemm_mainloop(A, B, As, Bs, bm, bn, N, K, F);
    gemm_store(C, bm, bn, N, F);
}

// ---------------------------------------------------------------------------
// Fused RMSNorm (over HD=128) + interleaved-pair RoPE, in place.
// ---------------------------------------------------------------------------
__global__ __launch_bounds__(256) void rmsnorm_rope_kernel(float* __restrict__ data,
                                                           const float* __restrict__ scale,
                                                           const float* __restrict__ cosT,
                                                           const float* __restrict__ sinT,
                                                           int nheads, int total_rows) {
    const int warp = threadIdx.x >> 5;
    const int lane = threadIdx.x & 31;
    const int row = blockIdx.x * 8 + warp;
    if (row >= total_rows) return;
    const int t = (row / nheads) % T_;

    float4* p = (float4*)(data + (size_t)row * HD_);
    float4 x = p[lane];
    float ss = x.x * x.x + x.y * x.y + x.z * x.z + x.w * x.w;
#pragma unroll
    for (int o = 16; o > 0; o >>= 1) ss += __shfl_xor_sync(0xffffffffu, ss, o);
    const float rinv = rsqrtf(ss * (1.0f / HD_) + 1e-6f);

    const int d0 = lane * 4;
    float4 sc = *(const float4*)(scale + d0);
    float n0 = x.x * rinv * sc.x;
    float n1 = x.y * rinv * sc.y;
    float n2 = x.z * rinv * sc.z;
    float n3 = x.w * rinv * sc.w;

    const float c0 = cosT[(size_t)t * HD_ + d0];
    const float s0 = sinT[(size_t)t * HD_ + d0];
    const float c1 = cosT[(size_t)t * HD_ + d0 + 2];
    const float s1 = sinT[(size_t)t * HD_ + d0 + 2];

    float4 r;
    r.x = n0 * c0 - n1 * s0;
    r.y = n1 * c0 + n0 * s0;
    r.z = n2 * c1 - n3 * s1;
    r.w = n3 * c1 + n2 * s1;
    p[lane] = r;
}

// ---------------------------------------------------------------------------
// Tensor-core causal GQA flash attention (TF32 mma, online softmax).
// Block: 256 thr = 8 warps; 128 query rows/block (16 per warp), 64-key tiles.
// ---------------------------------------------------------------------------
#define FA_PAD  132
#define FA_PPAD 68
#define FA_SMEM ((128 * FA_PAD + 64 * FA_PAD + 64 * FA_PAD + 8 * 16 * FA_PPAD) * 4)

__global__ __launch_bounds__(256, 1) void flash_tc(const float* __restrict__ q,
                                                   const float* __restrict__ k,
                                                   const float* __restrict__ v,
                                                   float* __restrict__ o) {
    extern __shared__ unsigned fsm[];
    unsigned* Qs = fsm;
    unsigned* Ks = Qs + 128 * FA_PAD;
    unsigned* Vs = Ks + 64 * FA_PAD;
    unsigned* Psw = Vs + 64 * FA_PAD + (threadIdx.x >> 5) * 16 * FA_PPAD;

    const int tid  = threadIdx.x;
    const int warp = tid >> 5;
    const int lane = tid & 31;
    const int la3  = lane & 3;
    const int r    = lane >> 2;
    const int bh = blockIdx.y;
    const int b = bh >> 4;
    const int h = bh & 15;
    const int g = h >> 2;
    const int qb = (gridDim.x - 1) - blockIdx.x;
    const int qbase = qb * 128;
    const int wm = warp * 16;

    const float sscale = 0.08838834764831845f;

    for (int i = tid; i < 128 * 32; i += 256) {
        const int row = i >> 5, c4 = (i & 31) * 4;
        float4 t = *(const float4*)(q + ((size_t)(b * T_ + qbase + row) * H_ + h) * HD_ + c4);
        uint4 u = {f2tf(t.x * sscale), f2tf(t.y * sscale), f2tf(t.z * sscale), f2tf(t.w * sscale)};
        *(uint4*)&Qs[row * FA_PAD + c4] = u;
    }
    __syncthreads();

    float m0 = -1e30f, m1 = -1e30f, l0 = 0.f, l1 = 0.f;
    float acc[16][4];
#pragma unroll
    for (int ns = 0; ns < 16; ns++)
#pragma unroll
        for (int i = 0; i < 4; i++) acc[ns][i] = 0.f;

    const int row0 = qbase + wm + r;
    const int ntiles = (qb + 1) * 2;

    for (int j = 0; j < ntiles; j++) {
        const int kbase = j * 64;
        for (int i = tid; i < 64 * 32; i += 256) {
            const int row = i >> 5, c4 = (i & 31) * 4;
            const size_t gi = ((size_t)(b * T_ + kbase + row) * KV_ + g) * HD_ + c4;
            float4 kt = *(const float4*)(k + gi);
            float4 vt = *(const float4*)(v + gi);
            uint4 ku = {f2tf(kt.x), f2tf(kt.y), f2tf(kt.z), f2tf(kt.w)};
            uint4 vu = {f2tf(vt.x), f2tf(vt.y), f2tf(vt.z), f2tf(vt.w)};
            *(uint4*)&Ks[row * FA_PAD + c4] = ku;
            *(uint4*)&Vs[row * FA_PAD + c4] = vu;
        }
        __syncthreads();

        const bool active = (kbase <= qbase + wm + 15);
        if (active) {
            float s[8][4];
#pragma unroll
            for (int ns = 0; ns < 8; ns++)
#pragma unroll
                for (int i = 0; i < 4; i++) s[ns][i] = 0.f;

#pragma unroll
            for (int kc = 0; kc < 16; kc++) {
                unsigned a[4];
                const unsigned* ap = Qs + (wm + r) * FA_PAD + kc * 8 + la3;
                a[0] = ap[0];
                a[1] = ap[8 * FA_PAD];
                a[2] = ap[4];
                a[3] = ap[8 * FA_PAD + 4];
#pragma unroll
                for (int ns = 0; ns < 8; ns++) {
                    unsigned bf[2];
                    const unsigned* bp = Ks + (ns * 8 + r) * FA_PAD + kc * 8 + la3;
                    bf[0] = bp[0];
                    bf[1] = bp[4];
                    MMA_TF32(s[ns], a, bf);
                }
            }

            if (kbase + 63 > qbase + wm) {
#pragma unroll
                for (int ns = 0; ns < 8; ns++) {
                    const int col = kbase + ns * 8 + la3 * 2;
                    if (col > row0)     s[ns][0] = -1e30f;
                    if (col + 1 > row0) s[ns][1] = -1e30f;
                    if (col > row0 + 8)     s[ns][2] = -1e30f;
                    if (col + 1 > row0 + 8) s[ns][3] = -1e30f;
                }
            }

            float mx0 = -1e30f, mx1 = -1e30f;
#pragma unroll
            for (int ns = 0; ns < 8; ns++) {
                mx0 = fmaxf(mx0, fmaxf(s[ns][0], s[ns][1]));
                mx1 = fmaxf(mx1, fmaxf(s[ns][2], s[ns][3]));
            }
            mx0 = fmaxf(mx0, __shfl_xor_sync(0xffffffffu, mx0, 1));
            mx0 = fmaxf(mx0, __shfl_xor_sync(0xffffffffu, mx0, 2));
            mx1 = fmaxf(mx1, __shfl_xor_sync(0xffffffffu, mx1, 1));
            mx1 = fmaxf(mx1, __shfl_xor_sync(0xffffffffu, mx1, 2));

            const float mn0 = fmaxf(m0, mx0);
            const float mn1 = fmaxf(m1, mx1);
            const float al0 = __expf(m0 - mn0);
            const float al1 = __expf(m1 - mn1);
            m0 = mn0; m1 = mn1;

            float sum0 = 0.f, sum1 = 0.f;
#pragma unroll
            for (int ns = 0; ns < 8; ns++) {
                float p0 = __expf(s[ns][0] - mn0);
                float p1 = __expf(s[ns][1] - mn0);
                float p2 = __expf(s[ns][2] - mn1);
                float p3 = __expf(s[ns][3] - mn1);
                sum0 += p0 + p1;
                sum1 += p2 + p3;
                uint2 u0 = {f2tf(p0), f2tf(p1)};
                uint2 u1 = {f2tf(p2), f2tf(p3)};
                *(uint2*)&Psw[r * FA_PPAD + ns * 8 + la3 * 2] = u0;
                *(uint2*)&Psw[(r + 8) * FA_PPAD + ns * 8 + la3 * 2] = u1;
            }
            sum0 += __shfl_xor_sync(0xffffffffu, sum0, 1);
            sum0 += __shfl_xor_sync(0xffffffffu, sum0, 2);
            sum1 += __shfl_xor_sync(0xffffffffu, sum1, 1);
            sum1 += __shfl_xor_sync(0xffffffffu, sum1, 2);
            l0 = l0 * al0 + sum0;
            l1 = l1 * al1 + sum1;

#pragma unroll
            for (int ns = 0; ns < 16; ns++) {
                acc[ns][0] *= al0; acc[ns][1] *= al0;
                acc[ns][2] *= al1; acc[ns][3] *= al1;
            }
            __syncwarp();

#pragma unroll
            for (int kc = 0; kc < 8; kc++) {
                unsigned a[4];
                const unsigned* ap = Psw + r * FA_PPAD + kc * 8 + la3;
                a[0] = ap[0];
                a[1] = ap[8 * FA_PPAD];
                a[2] = ap[4];
                a[3] = ap[8 * FA_PPAD + 4];
#pragma unroll
                for (int ns = 0; ns < 16; ns++) {
                    unsigned bf[2];
                    const unsigned* bp = Vs + (kc * 8 + la3) * FA_PAD + ns * 8 + r;
                    bf[0] = bp[0];
                    bf[1] = bp[4 * FA_PAD];
                    MMA_TF32(acc[ns], a, bf);
                }
            }
        }
        __syncthreads();
    }

    const float inv0 = 1.0f / l0;
    const float inv1 = 1.0f / l1;
    float* o0 = o + ((size_t)(b * T_ + row0) * H_ + h) * HD_;
    float* o1 = o + ((size_t)(b * T_ + row0 + 8) * H_ + h) * HD_;
#pragma unroll
    for (int ns = 0; ns < 16; ns++) {
        const int col = ns * 8 + la3 * 2;
        float2 v0 = {acc[ns][0] * inv0, acc[ns][1] * inv0};
        float2 v1 = {acc[ns][2] * inv1, acc[ns][3] * inv1};
        *(float2*)(o0 + col) = v0;
        *(float2*)(o1 + col) = v1;
    }
}

// ---------------------------------------------------------------------------
extern "C" void kernel_launch(void* const* d_in, const int* in_sizes, int n_in,
                              void* d_out, int out_size) {
    const float* x       = (const float*)d_in[0];
    const float* Wq      = (const float*)d_in[1];
    const float* Wk      = (const float*)d_in[2];
    const float* Wv      = (const float*)d_in[3];
    const float* Wo      = (const float*)d_in[4];
    const float* q_scale = (const float*)d_in[5];
    const float* k_scale = (const float*)d_in[6];
    const float* cosT    = (const float*)d_in[7];
    const float* sinT    = (const float*)d_in[8];
    float* out = (float*)d_out;

    float *q, *k, *v, *ao;
    cudaGetSymbolAddress((void**)&q,  g_q);
    cudaGetSymbolAddress((void**)&k,  g_k);
    cudaGetSymbolAddress((void**)&v,  g_v);
    cudaGetSymbolAddress((void**)&ao, g_o);

    const int M = B_ * T_;  // 4096

    cudaFuncSetAttribute(qkv_gemm, cudaFuncAttributeMaxDynamicSharedMemorySize, GEMM_SMEM);
    cudaFuncSetAttribute(gemm_tf32, cudaFuncAttributeMaxDynamicSharedMemorySize, GEMM_SMEM);
    cudaFuncSetAttribute(flash_tc, cudaFuncAttributeMaxDynamicSharedMemorySize, FA_SMEM);

    // Combined QKV projections (one launch, 768 blocks)
    qkv_gemm<<<768, 256, GEMM_SMEM>>>(x, Wq, Wk, Wv, q, k, v);

    // RMSNorm + RoPE on q and k (in place)
    rmsnorm_rope_kernel<<<(M * H_) / 8, 256>>>(q, q_scale, cosT, sinT, H_, M * H_);
    rmsnorm_rope_kernel<<<(M * KV_) / 8, 256>>>(k, k_scale, cosT, sinT, KV_, M * KV_);

    // Tensor-core flash attention
    flash_tc<<<dim3(T_ / 128, B_ * H_), 256, FA_SMEM>>>(q, k, v, ao);

    // Output projection
    gemm_tf32<<<dim3(D_ / 128, M / 128), 256, GEMM_SMEM>>>(ao, Wo, out, M, D_, H_ * HD_);
}